// round 12
// baseline (speedup 1.0000x reference)
#include <cuda_runtime.h>
#include <cuda_fp16.h>
#include <cstdint>

// out[65536,64] = xa[65536,256]@wa[256,64] + xb[65536,256]@wb[256,64]
// Single-term fp16: out = fp16(x) @ fp16(w), fp32 accum.
//   error = sum(dx*w) + sum(x*dw) ~ sqrt(2)*2.07e-4 ~ 2.9e-4 << 1e-3.
// mma.sync.m16n8k16.f32.f16.f16.f32, 8 MMA per warp per 16-k step.
// B: LDG.64 from L1-resident 64 KB fragment image (warp-contiguous 256 B).
// A: warp-private 2-stage cp.async ring (16 rows x 32 k fp32, seg-XOR
//    swizzle, structural-min LDS). No CTA barriers; __syncwarp only.
// CTA: 256 thr (8 warps x 16 rows), grid 512, smem 32 KB -> 3 CTAs/SM.

#define M_TILE  128
#define NCHUNK  16                  // chunks of 32 k
#define STAGEB  2048                // 16 rows * 128 B
#define WST     (2 * STAGEB)        // 4096 B per warp
#define SMEM_BYTES (8 * WST)        // 32768

// fragment-packed B: index (t*8+ni)*32+L -> uint2 {b0,b1}, t = k-step 0..31
//   b0 = wh{k0,k0+1}, b1 = wh{k0+8,k0+9}; k0 = t*16+(L&3)*2, n = ni*8+(L>>2)
__device__ __align__(16) uint2 g_wfrag[32 * 8 * 32];   // 64 KB

__device__ __forceinline__ uint32_t h2pack(float lo, float hi) {
    uint32_t r;
    asm("cvt.rn.f16x2.f32 %0, %1, %2;" : "=r"(r) : "f"(hi), "f"(lo));
    return r;
}

__device__ __forceinline__ void mma16816(float* c, const uint32_t* a,
                                         uint32_t b0, uint32_t b1) {
    asm volatile(
        "mma.sync.aligned.m16n8k16.row.col.f32.f16.f16.f32 "
        "{%0,%1,%2,%3}, {%4,%5,%6,%7}, {%8,%9}, {%0,%1,%2,%3};"
        : "+f"(c[0]), "+f"(c[1]), "+f"(c[2]), "+f"(c[3])
        : "r"(a[0]), "r"(a[1]), "r"(a[2]), "r"(a[3]), "r"(b0), "r"(b1));
}

__device__ __forceinline__ uint32_t smem_u32(const void* p) {
    uint32_t a;
    asm("{ .reg .u64 t; cvta.to.shared.u64 t, %1; cvt.u32.u64 %0, t; }"
        : "=r"(a) : "l"(p));
    return a;
}

// stage addr of float word w (0..31) in row r (0..15): 16B-seg XOR swizzle
__device__ __forceinline__ uint32_t stoff(int r, int w) {
    return (uint32_t)(r * 128) +
           ((((uint32_t)w >> 2) ^ ((uint32_t)r & 7u)) << 4) +
           (((uint32_t)w & 3u) << 2);
}

// ---- pre-kernel: pack fp16(w) into fragment order (proven) ----
__global__ void wconv_kernel(const float* __restrict__ wa,
                             const float* __restrict__ wb) {
    int id = blockIdx.x * 256 + threadIdx.x;   // 0..8191
    int L  = id & 31;
    int ni = (id >> 5) & 7;
    int t  = id >> 8;                          // k-step 0..31
    int k0 = t * 16 + (L & 3) * 2;             // global k
    int n  = ni * 8 + (L >> 2);
    const float* __restrict__ w = (k0 < 256) ? wa : wb;
    int kk = k0 & 255;
    float v0 = w[kk * 64 + n];
    float v1 = w[(kk + 1) * 64 + n];
    float v8 = w[(kk + 8) * 64 + n];
    float v9 = w[(kk + 9) * 64 + n];
    g_wfrag[id] = make_uint2(h2pack(v0, v1), h2pack(v8, v9));
}

// ---- main kernel ----
__global__ void __launch_bounds__(256, 3)
sshe_mma_kernel(const float* __restrict__ xa, const float* __restrict__ xb,
                float* __restrict__ out) {
    extern __shared__ uint8_t smem[];          // 8 warp-private A rings
    const uint32_t sbase = smem_u32(smem);
    const int tid = threadIdx.x;
    const int L = tid & 31;
    const int wid = tid >> 5;
    const long long row0 = (long long)blockIdx.x * M_TILE;

    // cp.async: lane L owns row L>>1, segs (L&1)*4 + 0..3 (16B each)
    const int crow = L >> 1;
    const int cs0 = (L & 1) * 4;
    const uint32_t wbase = sbase + (uint32_t)(wid * WST);
    const size_t gArow = (size_t)(row0 + wid * 16 + crow) * 256;

    auto issue_chunk = [&](int c, int s) {
        const float* __restrict__ xsrc = (c < 8) ? xa : xb;
        const float* g = xsrc + gArow + (c & 7) * 32 + cs0 * 4;
        const uint32_t d = wbase + (uint32_t)(s * STAGEB + crow * 128);
#pragma unroll
        for (int i = 0; i < 4; i++) {
            asm volatile("cp.async.cg.shared.global [%0], [%1], 16;"
                         :: "r"(d + (((uint32_t)(cs0 + i) ^ ((uint32_t)crow & 7u)) << 4)),
                            "l"(g + i * 4) : "memory");
        }
        asm volatile("cp.async.commit_group;" ::: "memory");
    };

    // fragment read offsets (proven m16n8k16 A mapping)
    const int r0 = L >> 2;
    const int r1 = r0 + 8;
    const int w0 = (L & 3) * 2;
    uint32_t off[2][4];
#pragma unroll
    for (int ks = 0; ks < 2; ks++) {
        off[ks][0] = stoff(r0, ks * 16 + w0);
        off[ks][1] = stoff(r1, ks * 16 + w0);
        off[ks][2] = stoff(r0, ks * 16 + w0 + 8);
        off[ks][3] = stoff(r1, ks * 16 + w0 + 8);
    }

    float acc[8][4];
#pragma unroll
    for (int i = 0; i < 8; i++)
#pragma unroll
        for (int j = 0; j < 4; j++) acc[i][j] = 0.f;

    const uint2* __restrict__ Bg = g_wfrag;

    issue_chunk(0, 0);

    for (int c = 0; c < NCHUNK; c++) {
        const int s = c & 1;
        if (c + 1 < NCHUNK) {
            issue_chunk(c + 1, s ^ 1);
            asm volatile("cp.async.wait_group 1;" ::: "memory");
        } else {
            asm volatile("cp.async.wait_group 0;" ::: "memory");
        }
        __syncwarp();   // chunk c landed in this warp's stage s

        const uint8_t* st = smem + wid * WST + s * STAGEB;
#pragma unroll
        for (int ks = 0; ks < 2; ks++) {
            // B fragments from L1-resident global image, issued first
            const int bb = (c * 2 + ks) * 256 + L;
            uint2 B[8];
#pragma unroll
            for (int ni = 0; ni < 8; ni++) B[ni] = __ldg(&Bg[bb + ni * 32]);

            float2 d0 = *(const float2*)(st + off[ks][0]);
            float2 d1 = *(const float2*)(st + off[ks][1]);
            float2 d2 = *(const float2*)(st + off[ks][2]);
            float2 d3 = *(const float2*)(st + off[ks][3]);
            uint32_t ah[4];
            ah[0] = h2pack(d0.x, d0.y);
            ah[1] = h2pack(d1.x, d1.y);
            ah[2] = h2pack(d2.x, d2.y);
            ah[3] = h2pack(d3.x, d3.y);
#pragma unroll
            for (int ni = 0; ni < 8; ni++)
                mma16816(acc[ni], ah, B[ni].x, B[ni].y);
        }
        __syncwarp();   // stage s consumed by all lanes before reuse
    }

    // epilogue (proven): c0,c1 -> (row, ni*8+kk2+{0,1}); c2,c3 -> (row+8, ..)
    const int kk2 = (L & 3) * 2;
    const size_t grow = row0 + wid * 16 + (L >> 2);
#pragma unroll
    for (int ni = 0; ni < 8; ni++) {
        float* o0 = out + grow * 64 + ni * 8 + kk2;
        float* o1 = out + (grow + 8) * 64 + ni * 8 + kk2;
        *(float2*)o0 = make_float2(acc[ni][0], acc[ni][1]);
        *(float2*)o1 = make_float2(acc[ni][2], acc[ni][3]);
    }
}

extern "C" void kernel_launch(void* const* d_in, const int* in_sizes, int n_in,
                              void* d_out, int out_size) {
    const float* xa = (const float*)d_in[0];
    const float* xb = (const float*)d_in[1];
    const float* wa = (const float*)d_in[2];
    const float* wb = (const float*)d_in[3];
    float* out = (float*)d_out;

    cudaFuncSetAttribute(sshe_mma_kernel,
                         cudaFuncAttributeMaxDynamicSharedMemorySize,
                         SMEM_BYTES);

    wconv_kernel<<<32, 256>>>(wa, wb);

    const int batch = in_sizes[0] / 256;     // 65536
    sshe_mma_kernel<<<batch / M_TILE, 256, SMEM_BYTES>>>(xa, xb, out);
}

// round 13
// speedup vs baseline: 1.2216x; 1.2216x over previous
#include <cuda_runtime.h>
#include <cuda_fp16.h>
#include <cstdint>

// out[65536,64] = xa[65536,256]@wa[256,64] + xb[65536,256]@wb[256,64]
// Single-term fp16: out = fp16(x) @ fp16(w), fp32 accum. rel_err ~2.9e-4.
// mma.sync.m16n8k16.f32.f16.f16.f32.
// Structure = proven round-5 kernel (43.5us): A frags direct from global
// (register prefetch, now depth 2), B smem fragment image (now uint4
// ni-pairs -> LDS.128), zero CTA barriers in loop, 2 CTAs/SM.
// CTA: 128 rows x 64 cols, 8 warps, grid 512. K=512 in 16 chunks of 32.

#define NCHUNK 16
#define M_TILE 128

// fragment-packed B, uint4 per (t, nj=ni/2, L):
//   index (t*4+nj)*32 + L -> {b0(ni=2nj), b1(2nj), b0(2nj+1), b1(2nj+1)}
//   b0 = wh{k0,k0+1}, b1 = wh{k0+8,k0+9}; k0 = t*16+(L&3)*2, n = ni*8+(L>>2)
__device__ __align__(16) uint4 g_wfrag[32 * 4 * 32];   // 64 KB

__device__ __forceinline__ uint32_t h2pack(float lo, float hi) {
    uint32_t r;
    asm("cvt.rn.f16x2.f32 %0, %1, %2;" : "=r"(r) : "f"(hi), "f"(lo));
    return r;
}

__device__ __forceinline__ void mma16816(float* c, const uint32_t* a,
                                         uint32_t b0, uint32_t b1) {
    asm volatile(
        "mma.sync.aligned.m16n8k16.row.col.f32.f16.f16.f32 "
        "{%0,%1,%2,%3}, {%4,%5,%6,%7}, {%8,%9}, {%0,%1,%2,%3};"
        : "+f"(c[0]), "+f"(c[1]), "+f"(c[2]), "+f"(c[3])
        : "r"(a[0]), "r"(a[1]), "r"(a[2]), "r"(a[3]), "r"(b0), "r"(b1));
}

// ---- pre-kernel: pack fp16(w) into uint4 ni-pair fragment order ----
__global__ void wconv_kernel(const float* __restrict__ wa,
                             const float* __restrict__ wb) {
    int id = blockIdx.x * 256 + threadIdx.x;   // 0..4095
    int L  = id & 31;
    int nj = (id >> 5) & 3;
    int t  = id >> 7;                          // k-step 0..31
    int k0 = t * 16 + (L & 3) * 2;             // global k
    const float* __restrict__ w = (k0 < 256) ? wa : wb;
    int kk = k0 & 255;
    int ne = nj * 16 + (L >> 2);               // n of ni=2nj
    int no = ne + 8;                           // n of ni=2nj+1
    uint4 r;
    r.x = h2pack(w[kk * 64 + ne], w[(kk + 1) * 64 + ne]);
    r.y = h2pack(w[(kk + 8) * 64 + ne], w[(kk + 9) * 64 + ne]);
    r.z = h2pack(w[kk * 64 + no], w[(kk + 1) * 64 + no]);
    r.w = h2pack(w[(kk + 8) * 64 + no], w[(kk + 9) * 64 + no]);
    g_wfrag[id] = r;
}

// ---- main kernel ----
__global__ void __launch_bounds__(256, 2)
sshe_mma_kernel(const float* __restrict__ xa, const float* __restrict__ xb,
                float* __restrict__ out) {
    extern __shared__ uint4 sB[];   // 4096 entries, verbatim g_wfrag
    const int tid = threadIdx.x;
    const int L = tid & 31;
    const int wid = tid >> 5;

    // copy B fragments to smem (identity layout)
    {
        const uint4* src = (const uint4*)g_wfrag;
#pragma unroll
        for (int i = 0; i < 16; i++) sB[tid + i * 256] = src[tid + i * 256];
    }
    __syncthreads();

    // A fragment coordinates (proven round-5 mapping)
    const int row = blockIdx.x * M_TILE + wid * 16 + (L >> 2);
    const int kk2 = (L & 3) * 2;
    const size_t roff0 = (size_t)row * 256 + kk2;
    const size_t roff1 = (size_t)(row + 8) * 256 + kk2;

    float acc[8][4];
#pragma unroll
    for (int i = 0; i < 8; i++)
#pragma unroll
        for (int j = 0; j < 4; j++) acc[i][j] = 0.f;

    // chunk c (32 k): slots per ks: (row,k0),(row+8,k0),(row,k0+8),(row+8,k0+8)
    float2 st[3][8];
    auto load_chunk = [&](int c, float2* dst) {
        const float* __restrict__ xsrc = (c < 8) ? xa : xb;
        const int kb = (c & 7) * 32;
        const float* p0 = xsrc + roff0 + kb;
        const float* p1 = xsrc + roff1 + kb;
#pragma unroll
        for (int ks = 0; ks < 2; ks++) {
            dst[ks * 4 + 0] = *(const float2*)(p0 + ks * 16);
            dst[ks * 4 + 1] = *(const float2*)(p1 + ks * 16);
            dst[ks * 4 + 2] = *(const float2*)(p0 + ks * 16 + 8);
            dst[ks * 4 + 3] = *(const float2*)(p1 + ks * 16 + 8);
        }
    };

    // depth-2 register prefetch pipeline, fully unrolled (static buf indices)
    load_chunk(0, st[0]);
    load_chunk(1, st[1]);

#pragma unroll
    for (int c = 0; c < NCHUNK; c++) {
        if (c + 2 < NCHUNK) load_chunk(c + 2, st[(c + 2) % 3]);
        const float2* cur = st[c % 3];
#pragma unroll
        for (int ks = 0; ks < 2; ks++) {
            uint32_t ah[4];
            ah[0] = h2pack(cur[ks * 4 + 0].x, cur[ks * 4 + 0].y);
            ah[1] = h2pack(cur[ks * 4 + 1].x, cur[ks * 4 + 1].y);
            ah[2] = h2pack(cur[ks * 4 + 2].x, cur[ks * 4 + 2].y);
            ah[3] = h2pack(cur[ks * 4 + 3].x, cur[ks * 4 + 3].y);
            const int base4 = (c * 2 + ks) * 128 + L;
#pragma unroll
            for (int nj = 0; nj < 4; nj++) {
                uint4 B = sB[base4 + nj * 32];
                mma16816(acc[2 * nj], ah, B.x, B.y);
                mma16816(acc[2 * nj + 1], ah, B.z, B.w);
            }
        }
    }

    // epilogue (proven): c0,c1 -> (row, ni*8+kk2+{0,1}); c2,c3 -> (row+8, ..)
#pragma unroll
    for (int ni = 0; ni < 8; ni++) {
        float* o0 = out + (size_t)row * 64 + ni * 8 + kk2;
        float* o1 = out + (size_t)(row + 8) * 64 + ni * 8 + kk2;
        *(float2*)o0 = make_float2(acc[ni][0], acc[ni][1]);
        *(float2*)o1 = make_float2(acc[ni][2], acc[ni][3]);
    }
}

extern "C" void kernel_launch(void* const* d_in, const int* in_sizes, int n_in,
                              void* d_out, int out_size) {
    const float* xa = (const float*)d_in[0];
    const float* xb = (const float*)d_in[1];
    const float* wa = (const float*)d_in[2];
    const float* wb = (const float*)d_in[3];
    float* out = (float*)d_out;

    cudaFuncSetAttribute(sshe_mma_kernel,
                         cudaFuncAttributeMaxDynamicSharedMemorySize, 65536);

    wconv_kernel<<<16, 256>>>(wa, wb);

    const int batch = in_sizes[0] / 256;     // 65536
    sshe_mma_kernel<<<batch / M_TILE, 256, 65536>>>(xa, xb, out);
}

// round 14
// speedup vs baseline: 1.4819x; 1.2130x over previous
#include <cuda_runtime.h>
#include <cuda_fp16.h>
#include <cstdint>

// out[65536,64] = xa[65536,256]@wa[256,64] + xb[65536,256]@wb[256,64]
// Single-term fp16: out = fp16(x) @ fp16(w), fp32 accum. rel_err ~2.9e-4.
// mma.sync.m16n8k16.f32.f16.f16.f32.
// K-PERMUTED fragments: within each 32-k chunk, thread q's fragment k's are
// the contiguous global floats [8q, 8q+8) -> A loads are 4x LDG.128 per
// chunk (32 wavefronts vs 64 for the naive fragment layout). B is packed
// with the same permutation by the pre-kernel.
// Structure otherwise = round-13 best: depth-2 register prefetch, uint4 B
// image in smem (LDS.128), zero CTA barriers in loop, 2 CTAs/SM, grid 512.

#define NCHUNK 16
#define M_TILE 128

// fragment-packed B, uint4 per (t, nj=ni/2, L):
//   index (t*4+nj)*32 + L; q=L&3, s=t&1, chunk=(t>>1)
//   k0 = chunk*32 + 8q + 4s (global, permuted layout)
//   {x,y} = ni=2nj:   x = wh{k0,k0+1},  y = wh{k0+2,k0+3}
//   {z,w} = ni=2nj+1: z = wh{k0,k0+1},  w = wh{k0+2,k0+3}
//   n(ni) = ni*8 + (L>>2)
__device__ __align__(16) uint4 g_wfrag[32 * 4 * 32];   // 64 KB

__device__ __forceinline__ uint32_t h2pack(float lo, float hi) {
    uint32_t r;
    asm("cvt.rn.f16x2.f32 %0, %1, %2;" : "=r"(r) : "f"(hi), "f"(lo));
    return r;
}

__device__ __forceinline__ void mma16816(float* c, const uint32_t* a,
                                         uint32_t b0, uint32_t b1) {
    asm volatile(
        "mma.sync.aligned.m16n8k16.row.col.f32.f16.f16.f32 "
        "{%0,%1,%2,%3}, {%4,%5,%6,%7}, {%8,%9}, {%0,%1,%2,%3};"
        : "+f"(c[0]), "+f"(c[1]), "+f"(c[2]), "+f"(c[3])
        : "r"(a[0]), "r"(a[1]), "r"(a[2]), "r"(a[3]), "r"(b0), "r"(b1));
}

// ---- pre-kernel: pack fp16(w), k-permuted, uint4 ni-pairs ----
__global__ void wconv_kernel(const float* __restrict__ wa,
                             const float* __restrict__ wb) {
    int id = blockIdx.x * 256 + threadIdx.x;   // 0..4095
    int L  = id & 31;
    int nj = (id >> 5) & 3;
    int t  = id >> 7;                          // k-step 0..31
    int q  = L & 3;
    int s  = t & 1;
    int k0 = (t >> 1) * 32 + 8 * q + 4 * s;    // permuted global k
    const float* __restrict__ w = (k0 < 256) ? wa : wb;
    int kk = k0 & 255;
    int ne = nj * 16 + (L >> 2);               // n of ni=2nj
    int no = ne + 8;                           // n of ni=2nj+1
    uint4 r;
    r.x = h2pack(w[kk * 64 + ne], w[(kk + 1) * 64 + ne]);
    r.y = h2pack(w[(kk + 2) * 64 + ne], w[(kk + 3) * 64 + ne]);
    r.z = h2pack(w[kk * 64 + no], w[(kk + 1) * 64 + no]);
    r.w = h2pack(w[(kk + 2) * 64 + no], w[(kk + 3) * 64 + no]);
    g_wfrag[id] = r;
}

// ---- main kernel ----
__global__ void __launch_bounds__(256, 2)
sshe_mma_kernel(const float* __restrict__ xa, const float* __restrict__ xb,
                float* __restrict__ out) {
    extern __shared__ uint4 sB[];   // 4096 entries, verbatim g_wfrag
    const int tid = threadIdx.x;
    const int L = tid & 31;
    const int wid = tid >> 5;

    // copy B fragments to smem (identity layout)
    {
        const uint4* src = (const uint4*)g_wfrag;
#pragma unroll
        for (int i = 0; i < 16; i++) sB[tid + i * 256] = src[tid + i * 256];
    }
    __syncthreads();

    // A coordinates: row pair (row, row+8); thread q owns floats [8q, 8q+8)
    const int row = blockIdx.x * M_TILE + wid * 16 + (L >> 2);
    const int q = L & 3;
    const size_t roff0 = (size_t)row * 256 + 8 * q;
    const size_t roff1 = (size_t)(row + 8) * 256 + 8 * q;

    float acc[8][4];
#pragma unroll
    for (int i = 0; i < 8; i++)
#pragma unroll
        for (int j = 0; j < 4; j++) acc[i][j] = 0.f;

    // chunk staging: v[0]=r0 floats 8q..+3, v[1]=r0 +4..+7, v[2]/v[3]=r1
    float4 st[3][4];
    auto load_chunk = [&](int c, float4* dst) {
        const float* __restrict__ xsrc = (c < 8) ? xa : xb;
        const int kb = (c & 7) * 32;
        const float* p0 = xsrc + roff0 + kb;
        const float* p1 = xsrc + roff1 + kb;
        dst[0] = *(const float4*)(p0);
        dst[1] = *(const float4*)(p0 + 4);
        dst[2] = *(const float4*)(p1);
        dst[3] = *(const float4*)(p1 + 4);
    };

    // depth-2 register prefetch pipeline, fully unrolled
    load_chunk(0, st[0]);
    load_chunk(1, st[1]);

#pragma unroll
    for (int c = 0; c < NCHUNK; c++) {
        if (c + 2 < NCHUNK) load_chunk(c + 2, st[(c + 2) % 3]);
        const float4* v = st[c % 3];
#pragma unroll
        for (int s = 0; s < 2; s++) {
            // step s: r0 data = v[s], r1 data = v[2+s]
            uint32_t ah[4];
            ah[0] = h2pack(v[s].x, v[s].y);         // pair q,   row
            ah[1] = h2pack(v[2 + s].x, v[2 + s].y); // pair q,   row+8
            ah[2] = h2pack(v[s].z, v[s].w);         // pair q+4, row
            ah[3] = h2pack(v[2 + s].z, v[2 + s].w); // pair q+4, row+8
            const int base4 = (c * 2 + s) * 128 + L;
#pragma unroll
            for (int nj = 0; nj < 4; nj++) {
                uint4 B = sB[base4 + nj * 32];
                mma16816(acc[2 * nj], ah, B.x, B.y);
                mma16816(acc[2 * nj + 1], ah, B.z, B.w);
            }
        }
    }

    // epilogue (C fragment layout unchanged by k-permutation)
    const int kk2 = (L & 3) * 2;
#pragma unroll
    for (int ni = 0; ni < 8; ni++) {
        float* o0 = out + (size_t)row * 64 + ni * 8 + kk2;
        float* o1 = out + (size_t)(row + 8) * 64 + ni * 8 + kk2;
        *(float2*)o0 = make_float2(acc[ni][0], acc[ni][1]);
        *(float2*)o1 = make_float2(acc[ni][2], acc[ni][3]);
    }
}

extern "C" void kernel_launch(void* const* d_in, const int* in_sizes, int n_in,
                              void* d_out, int out_size) {
    const float* xa = (const float*)d_in[0];
    const float* xb = (const float*)d_in[1];
    const float* wa = (const float*)d_in[2];
    const float* wb = (const float*)d_in[3];
    float* out = (float*)d_out;

    cudaFuncSetAttribute(sshe_mma_kernel,
                         cudaFuncAttributeMaxDynamicSharedMemorySize, 65536);

    wconv_kernel<<<16, 256>>>(wa, wb);

    const int batch = in_sizes[0] / 256;     // 65536
    sshe_mma_kernel<<<batch / M_TILE, 256, 65536>>>(xa, xb, out);
}

// round 15
// speedup vs baseline: 1.5100x; 1.0190x over previous
#include <cuda_runtime.h>
#include <cuda_fp16.h>
#include <cstdint>

// out[65536,64] = xa[65536,256]@wa[256,64] + xb[65536,256]@wb[256,64]
// Single-term fp16: out = fp16(x) @ fp16(w), fp32 accum. rel_err ~2.9e-4.
// mma.sync.m16n8k16.f32.f16.f16.f32, K-PERMUTED fragments (thread q owns
// contiguous floats -> LDG.128 A loads). 32-ROW WARPS: each warp computes
// two 16-row m-tiles, so every B LDS.128 feeds 2 MMAs (B wavefronts
// amortized 2x). Chunks of 16 k, depth-2 register prefetch, no CTA
// barriers in the loop, 2 CTAs/SM.
// CTA: 256 thr (8 warps x 32 rows = 256 rows), grid 256.

#define NCHUNK 32                   // chunks of 16 k
#define M_TILE 256

// fragment-packed B, uint4 per (t, nj, L), t = 16-k step 0..31:
//   index (t*4+nj)*32 + L; q=L&3, k0 = t*16 + 4q (permuted)
//   x = wh{k0,k0+1}|n_e, y = wh{k0+2,k0+3}|n_e   (n_e = nj*16 + (L>>2))
//   z = wh{k0,k0+1}|n_o, w = wh{k0+2,k0+3}|n_o   (n_o = n_e + 8)
__device__ __align__(16) uint4 g_wfrag[32 * 4 * 32];   // 64 KB

__device__ __forceinline__ uint32_t h2pack(float lo, float hi) {
    uint32_t r;
    asm("cvt.rn.f16x2.f32 %0, %1, %2;" : "=r"(r) : "f"(hi), "f"(lo));
    return r;
}

__device__ __forceinline__ void mma16816(float* c, const uint32_t* a,
                                         uint32_t b0, uint32_t b1) {
    asm volatile(
        "mma.sync.aligned.m16n8k16.row.col.f32.f16.f16.f32 "
        "{%0,%1,%2,%3}, {%4,%5,%6,%7}, {%8,%9}, {%0,%1,%2,%3};"
        : "+f"(c[0]), "+f"(c[1]), "+f"(c[2]), "+f"(c[3])
        : "r"(a[0]), "r"(a[1]), "r"(a[2]), "r"(a[3]), "r"(b0), "r"(b1));
}

// ---- pre-kernel: pack fp16(w), k-permuted, uint4 ni-pairs ----
__global__ void wconv_kernel(const float* __restrict__ wa,
                             const float* __restrict__ wb) {
    int id = blockIdx.x * 256 + threadIdx.x;   // 0..4095
    int L  = id & 31;
    int nj = (id >> 5) & 3;
    int t  = id >> 7;                          // 16-k step 0..31
    int q  = L & 3;
    int k0 = t * 16 + 4 * q;                   // permuted global k
    const float* __restrict__ w = (k0 < 256) ? wa : wb;
    int kk = k0 & 255;
    int ne = nj * 16 + (L >> 2);
    int no = ne + 8;
    uint4 r;
    r.x = h2pack(w[kk * 64 + ne], w[(kk + 1) * 64 + ne]);
    r.y = h2pack(w[(kk + 2) * 64 + ne], w[(kk + 3) * 64 + ne]);
    r.z = h2pack(w[kk * 64 + no], w[(kk + 1) * 64 + no]);
    r.w = h2pack(w[(kk + 2) * 64 + no], w[(kk + 3) * 64 + no]);
    g_wfrag[id] = r;
}

// ---- main kernel ----
__global__ void __launch_bounds__(256, 2)
sshe_mma_kernel(const float* __restrict__ xa, const float* __restrict__ xb,
                float* __restrict__ out) {
    extern __shared__ uint4 sB[];   // 4096 entries, verbatim g_wfrag
    const int tid = threadIdx.x;
    const int L = tid & 31;
    const int wid = tid >> 5;

    // copy B fragments to smem (identity layout)
    {
        const uint4* src = (const uint4*)g_wfrag;
#pragma unroll
        for (int i = 0; i < 16; i++) sB[tid + i * 256] = src[tid + i * 256];
    }
    __syncthreads();

    // A coordinates: warp owns rows [wid*32, wid*32+32); thread's base rows:
    //   mi=0: r = wid*32 + (L>>2) and r+8;  mi=1: +16.
    const int q = L & 3;
    const size_t rA = (size_t)(blockIdx.x * M_TILE + wid * 32 + (L >> 2));
    const size_t ro[4] = {                       // [mi*2 + (0:+0, 1:+8)]
        rA * 256 + 4 * q, (rA + 8) * 256 + 4 * q,
        (rA + 16) * 256 + 4 * q, (rA + 24) * 256 + 4 * q};

    float acc[2][8][4];
#pragma unroll
    for (int m = 0; m < 2; m++)
#pragma unroll
        for (int i = 0; i < 8; i++)
#pragma unroll
            for (int j = 0; j < 4; j++) acc[m][i][j] = 0.f;

    // chunk staging: 4 float4 = rows {r, r+8, r+16, r+24}, floats [4q,4q+4)
    float4 st[3][4];
    auto load_chunk = [&](int c, float4* dst) {
        const float* __restrict__ xsrc = (c < 16) ? xa : xb;
        const int kb = (c & 15) * 16;
        dst[0] = *(const float4*)(xsrc + ro[0] + kb);
        dst[1] = *(const float4*)(xsrc + ro[1] + kb);
        dst[2] = *(const float4*)(xsrc + ro[2] + kb);
        dst[3] = *(const float4*)(xsrc + ro[3] + kb);
    };

    // depth-2 register prefetch, fully unrolled (static buffer indices)
    load_chunk(0, st[0]);
    load_chunk(1, st[1]);

#pragma unroll
    for (int c = 0; c < NCHUNK; c++) {
        if (c + 2 < NCHUNK) load_chunk(c + 2, st[(c + 2) % 3]);
        const float4* v = st[c % 3];

        // A fragments for both m-tiles (a0/a1 = k-pair 0, a2/a3 = k-pair 1)
        uint32_t ah0[4], ah1[4];
        ah0[0] = h2pack(v[0].x, v[0].y);
        ah0[1] = h2pack(v[1].x, v[1].y);
        ah0[2] = h2pack(v[0].z, v[0].w);
        ah0[3] = h2pack(v[1].z, v[1].w);
        ah1[0] = h2pack(v[2].x, v[2].y);
        ah1[1] = h2pack(v[3].x, v[3].y);
        ah1[2] = h2pack(v[2].z, v[2].w);
        ah1[3] = h2pack(v[3].z, v[3].w);

        const int base4 = c * 128 + L;
#pragma unroll
        for (int nj = 0; nj < 4; nj++) {
            uint4 B = sB[base4 + nj * 32];   // one LDS.128, feeds 4 MMAs
            mma16816(acc[0][2 * nj], ah0, B.x, B.y);
            mma16816(acc[0][2 * nj + 1], ah0, B.z, B.w);
            mma16816(acc[1][2 * nj], ah1, B.x, B.y);
            mma16816(acc[1][2 * nj + 1], ah1, B.z, B.w);
        }
    }

    // epilogue (proven C mapping, per m-tile)
    const int kk2 = (L & 3) * 2;
#pragma unroll
    for (int mi = 0; mi < 2; mi++) {
        const size_t grow = rA + mi * 16;
#pragma unroll
        for (int ni = 0; ni < 8; ni++) {
            float* o0 = out + grow * 64 + ni * 8 + kk2;
            float* o1 = out + (grow + 8) * 64 + ni * 8 + kk2;
            *(float2*)o0 = make_float2(acc[mi][ni][0], acc[mi][ni][1]);
            *(float2*)o1 = make_float2(acc[mi][ni][2], acc[mi][ni][3]);
        }
    }
}

extern "C" void kernel_launch(void* const* d_in, const int* in_sizes, int n_in,
                              void* d_out, int out_size) {
    const float* xa = (const float*)d_in[0];
    const float* xb = (const float*)d_in[1];
    const float* wa = (const float*)d_in[2];
    const float* wb = (const float*)d_in[3];
    float* out = (float*)d_out;

    cudaFuncSetAttribute(sshe_mma_kernel,
                         cudaFuncAttributeMaxDynamicSharedMemorySize, 65536);

    wconv_kernel<<<16, 256>>>(wa, wb);

    const int batch = in_sizes[0] / 256;     // 65536
    sshe_mma_kernel<<<batch / M_TILE, 256, 65536>>>(xa, xb, out);
}